// round 14
// baseline (speedup 1.0000x reference)
#include <cuda_runtime.h>
#include <cuda_fp16.h>
#include <cstdint>

// Problem constants (fixed by the dataset)
#define NN   100000
#define EE   3200000
#define FF   7
#define HH   128
#define DD   64
#define EPSV 1e-5f

#define SCAN_BS 1024
#define NBLK ((NN + SCAN_BS - 1) / SCAN_BS)

// ---------------- device scratch (static; no allocations) ----------------
__device__ float  g_A[NN * HH];     // node features fp32 (h / h0 / h1, in-place residual)
__device__ __half g_Bh[NN * HH];    // per-layer X@W scratch in fp16 (gather operand)
__device__ float  g_dinv[NN];
__device__ int    g_cnt[NN];
__device__ int    g_rowptr[NN + 1];
__device__ int    g_fill[NN];
__device__ int2   g_edge[EE];       // packed {src, coef-bits}
__device__ int    g_blksums[NBLK];

// ---------------- CSR build ----------------
__global__ void k_zero_cnt() {
    for (int i = blockIdx.x * blockDim.x + threadIdx.x; i < NN; i += gridDim.x * blockDim.x)
        g_cnt[i] = 0;
}

// edge_index is int32 (JAX x64 disabled: jnp.int64 request silently yields int32)
__global__ void k_hist(const int* __restrict__ ei) {
    for (int e = blockIdx.x * blockDim.x + threadIdx.x; e < EE; e += gridDim.x * blockDim.x) {
        int d = ei[EE + e];
        atomicAdd(&g_cnt[d], 1);
    }
}

__global__ void k_scan_local() {
    __shared__ int sh[SCAN_BS];
    int tid = threadIdx.x;
    int i = blockIdx.x * SCAN_BS + tid;
    int v = (i < NN) ? g_cnt[i] : 0;
    if (i < NN) g_dinv[i] = rsqrtf((float)v + 1.0f);   // fused dinv
    sh[tid] = v;
    __syncthreads();
    for (int off = 1; off < SCAN_BS; off <<= 1) {
        int t = (tid >= off) ? sh[tid - off] : 0;
        __syncthreads();
        sh[tid] += t;
        __syncthreads();
    }
    if (i < NN) g_rowptr[i] = sh[tid] - v;  // exclusive prefix within block
    if (tid == SCAN_BS - 1) g_blksums[blockIdx.x] = sh[tid];
}

__global__ void k_scan_blocks() {   // parallel scan over NBLK block sums
    __shared__ int sh[128];
    int t = threadIdx.x;
    int v = (t < NBLK) ? g_blksums[t] : 0;
    sh[t] = v;
    __syncthreads();
    for (int off = 1; off < 128; off <<= 1) {
        int u = (t >= off) ? sh[t - off] : 0;
        __syncthreads();
        sh[t] += u;
        __syncthreads();
    }
    if (t < NBLK) g_blksums[t] = sh[t] - v;  // exclusive
}

__global__ void k_scan_add() {
    int i = blockIdx.x * SCAN_BS + threadIdx.x;
    if (i < NN) {
        int r = g_rowptr[i] + g_blksums[blockIdx.x];
        g_rowptr[i] = r;
        g_fill[i] = r;
    }
    if (i == 0) g_rowptr[NN] = EE;
}

__global__ void k_scatter(const int* __restrict__ ei) {
    for (int e = blockIdx.x * blockDim.x + threadIdx.x; e < EE; e += gridDim.x * blockDim.x) {
        int s = ei[e];
        int d = ei[EE + e];
        int pos = atomicAdd(&g_fill[d], 1);
        float coef = g_dinv[s] * g_dinv[d];
        g_edge[pos] = make_int2(s, __float_as_int(coef));
    }
}

// ---------------- input projection: h = relu(x @ W_in + b_in) ----------------
__global__ void k_inproj(const float* __restrict__ x,
                         const float* __restrict__ Win,
                         const float* __restrict__ bin) {
    __shared__ float xs[8];
    int i = blockIdx.x;
    int t = threadIdx.x;  // 0..127
    if (t < FF) xs[t] = x[i * FF + t];
    __syncthreads();
    float acc = bin[t];
#pragma unroll
    for (int k = 0; k < FF; k++) acc = fmaf(xs[k], Win[k * HH + t], acc);
    g_A[i * HH + t] = fmaxf(acc, 0.0f);
}

// ---------------- helpers for tensor-core GEMM ----------------
__device__ __forceinline__ uint32_t s2u(const void* p) {
    return (uint32_t)__cvta_generic_to_shared(p);
}
__device__ __forceinline__ void ldsm_x4(uint32_t& r0, uint32_t& r1, uint32_t& r2, uint32_t& r3,
                                        uint32_t addr) {
    asm volatile("ldmatrix.sync.aligned.m8n8.x4.shared.b16 {%0,%1,%2,%3}, [%4];"
                 : "=r"(r0), "=r"(r1), "=r"(r2), "=r"(r3) : "r"(addr));
}
__device__ __forceinline__ void ldsm_x2t(uint32_t& r0, uint32_t& r1, uint32_t addr) {
    asm volatile("ldmatrix.sync.aligned.m8n8.x2.trans.shared.b16 {%0,%1}, [%2];"
                 : "=r"(r0), "=r"(r1) : "r"(addr));
}
__device__ __forceinline__ void mma16816(float* d, const uint32_t* a, const uint32_t* b) {
    asm volatile(
        "mma.sync.aligned.m16n8k16.row.col.f32.f16.f16.f32 "
        "{%0,%1,%2,%3}, {%4,%5,%6,%7}, {%8,%9}, {%0,%1,%2,%3};"
        : "+f"(d[0]), "+f"(d[1]), "+f"(d[2]), "+f"(d[3])
        : "r"(a[0]), "r"(a[1]), "r"(a[2]), "r"(a[3]), "r"(b[0]), "r"(b[1]));
}

// ---------------- fp16 tensor-core GEMM: g_Bh[N,DO] = half(g_A[N,128] @ W[128,DO]) ----
template <int DO>
__global__ void k_hgemm(const float* __restrict__ W) {
    const int SAP = HH + 8;
    const int SWP = DO + 8;
    extern __shared__ __half sm[];
    __half* sA = sm;                 // [128][SAP]
    __half* sW = sm + 128 * SAP;     // [128][SWP]

    int tid = threadIdx.x;           // 256
    int wid = tid >> 5, lane = tid & 31;
    int rowBase = blockIdx.x * 128;

    // load A tile (128 x 128 fp32 -> fp16), 2 threads per row
    {
        int r = tid >> 1;
        int cbase = (tid & 1) * 64;
        const float* Arow = g_A + (size_t)(rowBase + r) * HH + cbase;
        bool valid = (rowBase + r) < NN;
        __half* dst = sA + r * SAP + cbase;
#pragma unroll
        for (int i = 0; i < 16; i++) {
            float4 v = valid ? *(const float4*)(Arow + i * 4) : make_float4(0.f, 0.f, 0.f, 0.f);
            *(__half2*)(dst + i * 4)     = __floats2half2_rn(v.x, v.y);
            *(__half2*)(dst + i * 4 + 2) = __floats2half2_rn(v.z, v.w);
        }
    }
    // load W (128 x DO fp32 -> fp16), 2 threads per row
    {
        const int CPT = DO / 2;
        int r = tid >> 1;
        int cbase = (tid & 1) * CPT;
        const float* Wrow = W + r * DO + cbase;
        __half* dst = sW + r * SWP + cbase;
#pragma unroll
        for (int i = 0; i < CPT / 4; i++) {
            float4 v = *(const float4*)(Wrow + i * 4);
            *(__half2*)(dst + i * 4)     = __floats2half2_rn(v.x, v.y);
            *(__half2*)(dst + i * 4 + 2) = __floats2half2_rn(v.z, v.w);
        }
    }
    __syncthreads();

    const int NT = DO / 16;
    int warp_m = wid & 3, warp_n = wid >> 2;
    int m0 = warp_m * 32, n0 = warp_n * (DO / 2);

    float acc[2][NT][4];
#pragma unroll
    for (int mt = 0; mt < 2; mt++)
#pragma unroll
        for (int nt = 0; nt < NT; nt++)
#pragma unroll
            for (int q = 0; q < 4; q++) acc[mt][nt][q] = 0.0f;

    int lr = lane & 15;
    int lc = (lane >> 4) * 8;

#pragma unroll
    for (int k = 0; k < HH; k += 16) {
        uint32_t a[2][4];
#pragma unroll
        for (int mt = 0; mt < 2; mt++) {
            uint32_t addr = s2u(sA + (m0 + mt * 16 + lr) * SAP + k + lc);
            ldsm_x4(a[mt][0], a[mt][1], a[mt][2], a[mt][3], addr);
        }
        uint32_t b[NT][2];
#pragma unroll
        for (int nt = 0; nt < NT; nt++) {
            uint32_t addr = s2u(sW + (k + lr) * SWP + n0 + nt * 8);
            ldsm_x2t(b[nt][0], b[nt][1], addr);
        }
#pragma unroll
        for (int mt = 0; mt < 2; mt++)
#pragma unroll
            for (int nt = 0; nt < NT; nt++)
                mma16816(acc[mt][nt], a[mt], b[nt]);
    }

    __half2* Ch = (__half2*)g_Bh;
    int rq = lane >> 2;
    int cq = (lane & 3) * 2;
#pragma unroll
    for (int mt = 0; mt < 2; mt++) {
#pragma unroll
        for (int nt = 0; nt < NT; nt++) {
            int col = n0 + nt * 8 + cq;
            int row0 = rowBase + m0 + mt * 16 + rq;
            int row1 = row0 + 8;
            if (row0 < NN)
                Ch[(row0 * DO + col) >> 1] = __floats2half2_rn(acc[mt][nt][0], acc[mt][nt][1]);
            if (row1 < NN)
                Ch[(row1 * DO + col) >> 1] = __floats2half2_rn(acc[mt][nt][2], acc[mt][nt][3]);
        }
    }
}

// ---------------- warp-per-node aggregation + fused epilogue --------------------------
// DO=128: lane owns 4 channels (uint2 of half2, 8B); DO=64: lane owns 2 channels (half2).
// No shared memory, no block barriers; edge metadata broadcast via shfl.
#define WPB 8   // warps (nodes) per block
template <int DO, bool FINAL>
__global__ void k_agg(const float* __restrict__ bias,
                      const float* __restrict__ gg,
                      const float* __restrict__ bb,
                      const float* __restrict__ mm,
                      const float* __restrict__ vv,
                      float* __restrict__ outp) {
    int wid = threadIdx.x >> 5, lane = threadIdx.x & 31;
    int i = blockIdx.x * WPB + wid;
    if (i >= NN) return;

    const int CPL = DO / 32;          // channels per lane: 4 or 2
    const __half* __restrict__ Bh = g_Bh;
    float di = g_dinv[i];
    float dii = di * di;

    float acc[CPL];
    {
        const __half2* selfrow = (const __half2*)(Bh + (size_t)i * DO) + lane * (CPL / 2);
#pragma unroll
        for (int q = 0; q < CPL / 2; q++) {
            float2 f = __half22float2(selfrow[q]);
            acc[2 * q]     = f.x * dii;
            acc[2 * q + 1] = f.y * dii;
        }
    }

    int beg = g_rowptr[i], end = g_rowptr[i + 1];
    for (int base = beg; base < end; base += 32) {
        int rem = end - base;
        int n = min(32, rem);
        int2 e = make_int2(0, 0);
        if (lane < n) e = g_edge[base + lane];
        for (int j = 0; j < n; j++) {
            int src  = __shfl_sync(0xffffffffu, e.x, j);
            float c  = __int_as_float(__shfl_sync(0xffffffffu, e.y, j));
            const __half2* row = (const __half2*)(Bh + (size_t)src * DO) + lane * (CPL / 2);
            if (CPL == 4) {
                uint2 rv = *(const uint2*)row;
                float2 f0 = __half22float2(*(__half2*)&rv.x);
                float2 f1 = __half22float2(*(__half2*)&rv.y);
                acc[0] = fmaf(f0.x, c, acc[0]);
                acc[1] = fmaf(f0.y, c, acc[1]);
                acc[2] = fmaf(f1.x, c, acc[2]);
                acc[3] = fmaf(f1.y, c, acc[3]);
            } else {
                float2 f = __half22float2(*row);
                acc[0] = fmaf(f.x, c, acc[0]);
                acc[1] = fmaf(f.y, c, acc[1]);
            }
        }
    }

    int c0 = lane * CPL;
    float y[CPL];
#pragma unroll
    for (int q = 0; q < CPL; q++) {
        float s = gg[c0 + q] * rsqrtf(vv[c0 + q] + EPSV);
        y[q] = (acc[q] + bias[c0 + q] - mm[c0 + q]) * s + bb[c0 + q];
    }
    if (FINAL) {
        float2* o = (float2*)(outp + (size_t)i * DO) + lane * (CPL / 2);
#pragma unroll
        for (int q = 0; q < CPL / 2; q++) o[q] = make_float2(y[2 * q], y[2 * q + 1]);
    } else {
        float4* Ares = (float4*)(g_A + (size_t)i * DO) + lane;  // CPL==4 here
        float4 r = *Ares;
        r.x += fmaxf(y[0], 0.0f);
        r.y += fmaxf(y[1], 0.0f);
        r.z += fmaxf(y[2], 0.0f);
        r.w += fmaxf(y[3], 0.0f);
        *Ares = r;
    }
}

// ---------------- host ----------------
extern "C" void kernel_launch(void* const* d_in, const int* in_sizes, int n_in,
                              void* d_out, int out_size) {
    const float* x    = (const float*)d_in[0];
    const int*   ei   = (const int*)d_in[1];   // int32! (JAX x64 disabled)
    const float* W_in = (const float*)d_in[2];
    const float* b_in = (const float*)d_in[3];
    const float* W0 = (const float*)d_in[4],  *b0 = (const float*)d_in[5];
    const float* g0 = (const float*)d_in[6],  *be0 = (const float*)d_in[7];
    const float* m0 = (const float*)d_in[8],  *v0 = (const float*)d_in[9];
    const float* W1 = (const float*)d_in[10], *b1 = (const float*)d_in[11];
    const float* g1 = (const float*)d_in[12], *be1 = (const float*)d_in[13];
    const float* m1 = (const float*)d_in[14], *v1 = (const float*)d_in[15];
    const float* W2 = (const float*)d_in[16], *b2 = (const float*)d_in[17];
    const float* g2 = (const float*)d_in[18], *be2 = (const float*)d_in[19];
    const float* m2 = (const float*)d_in[20], *v2 = (const float*)d_in[21];
    float* out = (float*)d_out;

    // dynamic smem sizes for the fp16 GEMMs (exceed 48KB static limit)
    const int SMEM_H = 128 * (HH + 8 + HH + 8) * (int)sizeof(__half);   // DO=128
    const int SMEM_D = 128 * (HH + 8 + DD + 8) * (int)sizeof(__half);   // DO=64
    cudaFuncSetAttribute(k_hgemm<HH>, cudaFuncAttributeMaxDynamicSharedMemorySize, SMEM_H);
    cudaFuncSetAttribute(k_hgemm<DD>, cudaFuncAttributeMaxDynamicSharedMemorySize, SMEM_D);

    // Fork: CSR build (depends only on edge_index) runs concurrently with
    // inproj + GEMM0 (depend only on x, W_in, W0). Join before agg layer 0.
    cudaStream_t s2;
    cudaStreamCreateWithFlags(&s2, cudaStreamNonBlocking);
    cudaEvent_t evFork, evJoin;
    cudaEventCreateWithFlags(&evFork, cudaEventDisableTiming);
    cudaEventCreateWithFlags(&evJoin, cudaEventDisableTiming);

    cudaEventRecord(evFork, 0);
    cudaStreamWaitEvent(s2, evFork, 0);

    // CSR chain on side stream
    k_zero_cnt<<<256, 256, 0, s2>>>();
    k_hist<<<1024, 256, 0, s2>>>(ei);
    k_scan_local<<<NBLK, SCAN_BS, 0, s2>>>();
    k_scan_blocks<<<1, 128, 0, s2>>>();
    k_scan_add<<<NBLK, SCAN_BS, 0, s2>>>();
    k_scatter<<<1024, 256, 0, s2>>>(ei);
    cudaEventRecord(evJoin, s2);

    // main stream: input projection + layer-0 GEMM
    k_inproj<<<NN, HH>>>(x, W_in, b_in);
    const int GB = (NN + 127) / 128;
    k_hgemm<HH><<<GB, 256, SMEM_H>>>(W0);

    // join: aggregation needs the CSR
    cudaStreamWaitEvent(0, evJoin, 0);

    const int GA = (NN + WPB - 1) / WPB;
    // layer 0
    k_agg<HH, false><<<GA, WPB * 32>>>(b0, g0, be0, m0, v0, nullptr);
    // layer 1
    k_hgemm<HH><<<GB, 256, SMEM_H>>>(W1);
    k_agg<HH, false><<<GA, WPB * 32>>>(b1, g1, be1, m1, v1, nullptr);
    // layer 2 (final)
    k_hgemm<DD><<<GB, 256, SMEM_D>>>(W2);
    k_agg<DD, true><<<GA, WPB * 32>>>(b2, g2, be2, m2, v2, out);
}